// round 16
// baseline (speedup 1.0000x reference)
#include <cuda_runtime.h>
#include <cuda_bf16.h>
#include <cstdint>

// Problem dims
constexpr int B = 8;
constexpr int N = 2048;
constexpr int D = 128;

// Scratch (device globals; no allocation allowed)
__device__ float g_hw[B * N * D];              // h @ W^T
__device__ float g_si[B * N];
__device__ float g_sj[B * N];
__device__ float g_ssort[B * N];               // sorted s_j per batch (ascending)
__device__ int   g_perm[B * N];                // original indices of sorted order
__device__ float g_F[B * (N + 1) * D];         // exclusive prefix of exp(s_j)*hw in sorted order
__device__ float g_G[B * (N + 1) * D];         // exclusive prefix of hw in sorted order
constexpr int NC = 16;                          // chunks per batch for scan
constexpr int CH = N / NC;                      // 128
__device__ float g_chF[B * NC * D];
__device__ float g_chG[B * NC * D];
__device__ int   g_k[B * N];                   // split index per row i
__device__ float g_c1[B * N];                  // exp(s_i)/Z_i
__device__ float g_c2[B * N];                  // 1/Z_i

// ---------------------------------------------------------------------------
// K1: hw = h @ W^T  (hw[n,e] = sum_d h[n,d]*W[e,d]), plus s_i = hw.a_i, s_j = hw.a_j
// 256 threads, tile: 64 rows x 128 cols, BK=16, micro-tile 8x4 per thread.
// ---------------------------------------------------------------------------
constexpr int BM = 64;
constexpr int BK = 16;

__global__ __launch_bounds__(256) void k_hw(const float* __restrict__ h,
                                            const float* __restrict__ W,
                                            const float* __restrict__ a) {
    __shared__ __align__(16) float hs[BM][BK];
    __shared__ __align__(16) float Wt[BK][132];   // padded: 132 words/row, 16B aligned rows

    const int block_row = blockIdx.x * BM;
    const int tid = threadIdx.x;
    const int tr = tid >> 5;   // warp id 0..7 -> row group
    const int tc = tid & 31;   // lane       -> col group

    float acc[8][4];
#pragma unroll
    for (int r = 0; r < 8; r++)
#pragma unroll
        for (int c = 0; c < 4; c++) acc[r][c] = 0.f;

    for (int k0 = 0; k0 < D; k0 += BK) {
        // stage h tile: 64 rows x 16 k, one float4 per thread
        {
            int r = tid >> 2;
            int kq = (tid & 3) * 4;
            float4 v = *reinterpret_cast<const float4*>(&h[(size_t)(block_row + r) * D + k0 + kq]);
            *reinterpret_cast<float4*>(&hs[r][kq]) = v;
        }
        // stage W tile transposed: Wt[kk][e] = W[e][k0+kk]
        {
            int kk = tid & 15;
            int e0 = tid >> 4;
#pragma unroll
            for (int p = 0; p < 8; p++) {
                int e = e0 + p * 16;
                Wt[kk][e] = W[(size_t)e * D + k0 + kk];
            }
        }
        __syncthreads();
#pragma unroll
        for (int kk = 0; kk < BK; kk++) {
            float hv[8];
#pragma unroll
            for (int r = 0; r < 8; r++) hv[r] = hs[tr * 8 + r][kk];   // broadcast
            float4 w4 = *reinterpret_cast<const float4*>(&Wt[kk][tc * 4]);
            float wv[4] = {w4.x, w4.y, w4.z, w4.w};
#pragma unroll
            for (int r = 0; r < 8; r++)
#pragma unroll
                for (int c = 0; c < 4; c++)
                    acc[r][c] = fmaf(hv[r], wv[c], acc[r][c]);
        }
        __syncthreads();
    }

    // epilogue: write hw, compute s_i/s_j partials and warp-reduce
    float ai[4], aj[4];
#pragma unroll
    for (int c = 0; c < 4; c++) {
        ai[c] = __ldg(&a[tc * 4 + c]);
        aj[c] = __ldg(&a[D + tc * 4 + c]);
    }
    float pi[8], pj[8];
#pragma unroll
    for (int r = 0; r < 8; r++) {
        int row = block_row + tr * 8 + r;
        float4 o = make_float4(acc[r][0], acc[r][1], acc[r][2], acc[r][3]);
        *reinterpret_cast<float4*>(&g_hw[(size_t)row * D + tc * 4]) = o;
        float si = 0.f, sj = 0.f;
#pragma unroll
        for (int c = 0; c < 4; c++) {
            si = fmaf(acc[r][c], ai[c], si);
            sj = fmaf(acc[r][c], aj[c], sj);
        }
        pi[r] = si; pj[r] = sj;
    }
#pragma unroll
    for (int r = 0; r < 8; r++) {
#pragma unroll
        for (int off = 16; off > 0; off >>= 1) {
            pi[r] += __shfl_xor_sync(0xffffffffu, pi[r], off);
            pj[r] += __shfl_xor_sync(0xffffffffu, pj[r], off);
        }
        if (tc == r) {                      // lane r writes row r of this warp's group
            int row = block_row + tr * 8 + r;
            g_si[row] = pi[r];
            g_sj[row] = pj[r];
        }
    }
}

// ---------------------------------------------------------------------------
// K2: per-batch bitonic sort of s_j (ascending) with index payload, inclusive
// scan of exp(s_sorted), then per-row-i binary search -> k_i and coefficients.
// One block (1024 threads) per batch.
// ---------------------------------------------------------------------------
__global__ __launch_bounds__(1024) void k_sort() {
    __shared__ float key[N];
    __shared__ int   idx[N];
    __shared__ float ez[N];     // inclusive prefix of exp(key)

    const int b = blockIdx.x;
    const int tid = threadIdx.x;

    for (int i = tid; i < N; i += 1024) {
        key[i] = g_sj[b * N + i];
        idx[i] = i;
    }
    __syncthreads();

    // bitonic sort (ascending)
    for (int k = 2; k <= N; k <<= 1) {
        for (int j = k >> 1; j > 0; j >>= 1) {
            for (int i = tid; i < N; i += 1024) {
                int ixj = i ^ j;
                if (ixj > i) {
                    bool up = ((i & k) == 0);
                    float k0 = key[i], k1 = key[ixj];
                    if ((k0 > k1) == up) {
                        key[i] = k1; key[ixj] = k0;
                        int t = idx[i]; idx[i] = idx[ixj]; idx[ixj] = t;
                    }
                }
            }
            __syncthreads();
        }
    }

    // inclusive scan of exp(key) (Hillis-Steele, 2 elems/thread)
    const int i0 = tid, i1 = tid + 1024;
    ez[i0] = expf(key[i0]);
    ez[i1] = expf(key[i1]);
    __syncthreads();
    for (int off = 1; off < N; off <<= 1) {
        float a0 = ez[i0], a1 = ez[i1];
        float b0 = (i0 >= off) ? ez[i0 - off] : 0.f;
        float b1 = (i1 >= off) ? ez[i1 - off] : 0.f;
        __syncthreads();
        ez[i0] = a0 + b0;
        ez[i1] = a1 + b1;
        __syncthreads();
    }

    // store sorted keys/perm for the prefix kernels
    for (int i = tid; i < N; i += 1024) {
        g_ssort[b * N + i] = key[i];
        g_perm[b * N + i]  = idx[i];
    }

    // per-row coefficients: k_i, c1 = e^{si}/Z, c2 = 1/Z
    const float EzN = ez[N - 1];
    for (int i = tid; i < N; i += 1024) {
        float si = g_si[b * N + i];
        float t = -si;
        int lo = 0, hi = N;
        while (lo < hi) {
            int mid = (lo + hi) >> 1;
            if (key[mid] <= t) lo = mid + 1; else hi = mid;
        }
        int k = lo;                              // #{j : s_j <= -s_i}
        float esi = expf(si);
        float ezk = (k > 0) ? ez[k - 1] : 0.f;
        float Z = fmaf(esi, EzN - ezk, (float)k); // Z >= N, never 0
        g_k[b * N + i]  = k;
        g_c1[b * N + i] = esi / Z;
        g_c2[b * N + i] = 1.f / Z;
    }
}

// ---------------------------------------------------------------------------
// K3a: per-chunk totals of F (exp(s)*hw) and G (hw) in sorted order
// ---------------------------------------------------------------------------
__global__ __launch_bounds__(128) void k_chunks() {
    const int b = blockIdx.y, c = blockIdx.x, d = threadIdx.x;
    __shared__ float sw[CH];
    __shared__ int   sp[CH];
    {
        int r = d;  // CH == blockDim.x == 128
        sw[r] = expf(g_ssort[b * N + c * CH + r]);
        sp[r] = g_perm[b * N + c * CH + r];
    }
    __syncthreads();
    float aF = 0.f, aG = 0.f;
#pragma unroll 4
    for (int r = 0; r < CH; r++) {
        float v = g_hw[((size_t)b * N + sp[r]) * D + d];
        aF = fmaf(sw[r], v, aF);
        aG += v;
    }
    g_chF[(b * NC + c) * D + d] = aF;
    g_chG[(b * NC + c) * D + d] = aG;
}

// K3b: exclusive scan of chunk totals (tiny)
__global__ __launch_bounds__(128) void k_scanchunks() {
    const int b = blockIdx.x, d = threadIdx.x;
    float rF = 0.f, rG = 0.f;
#pragma unroll
    for (int c = 0; c < NC; c++) {
        int o = (b * NC + c) * D + d;
        float tF = g_chF[o], tG = g_chG[o];
        g_chF[o] = rF; g_chG[o] = rG;
        rF += tF; rG += tG;
    }
}

// K3c: write full exclusive prefixes F[k], G[k] (k = 0..N)
__global__ __launch_bounds__(128) void k_prefix() {
    const int b = blockIdx.y, c = blockIdx.x, d = threadIdx.x;
    __shared__ float sw[CH];
    __shared__ int   sp[CH];
    {
        int r = d;
        sw[r] = expf(g_ssort[b * N + c * CH + r]);
        sp[r] = g_perm[b * N + c * CH + r];
    }
    __syncthreads();
    float aF = g_chF[(b * NC + c) * D + d];
    float aG = g_chG[(b * NC + c) * D + d];
#pragma unroll 4
    for (int r = 0; r < CH; r++) {
        int k = c * CH + r;
        g_F[((size_t)b * (N + 1) + k) * D + d] = aF;
        g_G[((size_t)b * (N + 1) + k) * D + d] = aG;
        float v = g_hw[((size_t)b * N + sp[r]) * D + d];
        aF = fmaf(sw[r], v, aF);
        aG += v;
    }
    if (c == NC - 1) {
        g_F[((size_t)b * (N + 1) + N) * D + d] = aF;
        g_G[((size_t)b * (N + 1) + N) * D + d] = aG;
    }
}

// ---------------------------------------------------------------------------
// K4: out[b,i,d] = relu(c1_i*(F_N[d]-F[k_i][d]) + c2_i*G[k_i][d])
// ---------------------------------------------------------------------------
constexpr int RI = 32;
__global__ __launch_bounds__(128) void k_out(float* __restrict__ out) {
    const int b = blockIdx.y;
    const int i0 = blockIdx.x * RI;
    const int d = threadIdx.x;
    const float FN = g_F[((size_t)b * (N + 1) + N) * D + d];
#pragma unroll 2
    for (int ii = 0; ii < RI; ii++) {
        int i = i0 + ii;
        int k = __ldg(&g_k[b * N + i]);
        float c1 = __ldg(&g_c1[b * N + i]);
        float c2 = __ldg(&g_c2[b * N + i]);
        size_t off = ((size_t)b * (N + 1) + k) * D + d;
        float num = fmaf(c1, FN - g_F[off], c2 * g_G[off]);
        out[((size_t)b * N + i) * D + d] = fmaxf(num, 0.f);
    }
}

// ---------------------------------------------------------------------------
extern "C" void kernel_launch(void* const* d_in, const int* in_sizes, int n_in,
                              void* d_out, int out_size) {
    const float* h = nullptr;
    const float* W = nullptr;
    const float* a = nullptr;
    for (int i = 0; i < n_in; i++) {
        if (in_sizes[i] == B * N * D)      h = (const float*)d_in[i];
        else if (in_sizes[i] == D * D)     W = (const float*)d_in[i];
        else if (in_sizes[i] == 2 * D)     a = (const float*)d_in[i];
    }
    float* out = (float*)d_out;

    k_hw<<<(B * N) / BM, 256>>>(h, W, a);
    k_sort<<<B, 1024>>>();
    k_chunks<<<dim3(NC, B), 128>>>();
    k_scanchunks<<<B, 128>>>();
    k_prefix<<<dim3(NC, B), 128>>>();
    k_out<<<dim3(N / RI, B), 128>>>(out);
}

// round 17
// speedup vs baseline: 1.0006x; 1.0006x over previous
#include <cuda_runtime.h>
#include <cuda_bf16.h>
#include <cstdint>

// Problem dims
constexpr int B = 8;
constexpr int N = 2048;
constexpr int D = 128;

// Scratch (device globals; no allocation allowed)
__device__ float g_hw[B * N * D];              // h @ W^T
__device__ float g_si[B * N];
__device__ float g_sj[B * N];
__device__ float g_ssort[B * N];               // sorted s_j per batch (ascending)
__device__ int   g_perm[B * N];                // original indices of sorted order
__device__ float g_F[B * (N + 1) * D];         // exclusive prefix of exp(s_j)*hw in sorted order
__device__ float g_G[B * (N + 1) * D];         // exclusive prefix of hw in sorted order
constexpr int NC = 16;                          // chunks per batch for scan
constexpr int CH = N / NC;                      // 128
__device__ float g_chF[B * NC * D];
__device__ float g_chG[B * NC * D];
__device__ int   g_k[B * N];                   // split index per row i
__device__ float g_c1[B * N];                  // exp(s_i)/Z_i
__device__ float g_c2[B * N];                  // 1/Z_i

// ---------------------------------------------------------------------------
// K1: hw = h @ W^T  (hw[n,e] = sum_d h[n,d]*W[e,d]), plus s_i = hw.a_i, s_j = hw.a_j
// 256 threads, tile: 64 rows x 128 cols, BK=16, micro-tile 8x4 per thread.
// ---------------------------------------------------------------------------
constexpr int BM = 64;
constexpr int BK = 16;

__global__ __launch_bounds__(256) void k_hw(const float* __restrict__ h,
                                            const float* __restrict__ W,
                                            const float* __restrict__ a) {
    __shared__ __align__(16) float hs[BM][BK];
    __shared__ __align__(16) float Wt[BK][132];   // padded: 132 words/row, 16B aligned rows

    const int block_row = blockIdx.x * BM;
    const int tid = threadIdx.x;
    const int tr = tid >> 5;   // warp id 0..7 -> row group
    const int tc = tid & 31;   // lane       -> col group

    float acc[8][4];
#pragma unroll
    for (int r = 0; r < 8; r++)
#pragma unroll
        for (int c = 0; c < 4; c++) acc[r][c] = 0.f;

    for (int k0 = 0; k0 < D; k0 += BK) {
        // stage h tile: 64 rows x 16 k, one float4 per thread
        {
            int r = tid >> 2;
            int kq = (tid & 3) * 4;
            float4 v = *reinterpret_cast<const float4*>(&h[(size_t)(block_row + r) * D + k0 + kq]);
            *reinterpret_cast<float4*>(&hs[r][kq]) = v;
        }
        // stage W tile transposed: Wt[kk][e] = W[e][k0+kk]
        {
            int kk = tid & 15;
            int e0 = tid >> 4;
#pragma unroll
            for (int p = 0; p < 8; p++) {
                int e = e0 + p * 16;
                Wt[kk][e] = W[(size_t)e * D + k0 + kk];
            }
        }
        __syncthreads();
#pragma unroll
        for (int kk = 0; kk < BK; kk++) {
            float hv[8];
#pragma unroll
            for (int r = 0; r < 8; r++) hv[r] = hs[tr * 8 + r][kk];   // broadcast
            float4 w4 = *reinterpret_cast<const float4*>(&Wt[kk][tc * 4]);
            float wv[4] = {w4.x, w4.y, w4.z, w4.w};
#pragma unroll
            for (int r = 0; r < 8; r++)
#pragma unroll
                for (int c = 0; c < 4; c++)
                    acc[r][c] = fmaf(hv[r], wv[c], acc[r][c]);
        }
        __syncthreads();
    }

    // epilogue: write hw, compute s_i/s_j partials and warp-reduce
    float ai[4], aj[4];
#pragma unroll
    for (int c = 0; c < 4; c++) {
        ai[c] = __ldg(&a[tc * 4 + c]);
        aj[c] = __ldg(&a[D + tc * 4 + c]);
    }
    float pi[8], pj[8];
#pragma unroll
    for (int r = 0; r < 8; r++) {
        int row = block_row + tr * 8 + r;
        float4 o = make_float4(acc[r][0], acc[r][1], acc[r][2], acc[r][3]);
        *reinterpret_cast<float4*>(&g_hw[(size_t)row * D + tc * 4]) = o;
        float si = 0.f, sj = 0.f;
#pragma unroll
        for (int c = 0; c < 4; c++) {
            si = fmaf(acc[r][c], ai[c], si);
            sj = fmaf(acc[r][c], aj[c], sj);
        }
        pi[r] = si; pj[r] = sj;
    }
#pragma unroll
    for (int r = 0; r < 8; r++) {
#pragma unroll
        for (int off = 16; off > 0; off >>= 1) {
            pi[r] += __shfl_xor_sync(0xffffffffu, pi[r], off);
            pj[r] += __shfl_xor_sync(0xffffffffu, pj[r], off);
        }
        if (tc == r) {                      // lane r writes row r of this warp's group
            int row = block_row + tr * 8 + r;
            g_si[row] = pi[r];
            g_sj[row] = pj[r];
        }
    }
}

// ---------------------------------------------------------------------------
// K2: per-batch bitonic sort of s_j (ascending) with index payload, inclusive
// scan of exp(s_sorted), then per-row-i binary search -> k_i and coefficients.
// One block (1024 threads) per batch.
// ---------------------------------------------------------------------------
__global__ __launch_bounds__(1024) void k_sort() {
    __shared__ float key[N];
    __shared__ int   idx[N];
    __shared__ float ez[N];     // inclusive prefix of exp(key)

    const int b = blockIdx.x;
    const int tid = threadIdx.x;

    for (int i = tid; i < N; i += 1024) {
        key[i] = g_sj[b * N + i];
        idx[i] = i;
    }
    __syncthreads();

    // bitonic sort (ascending)
    for (int k = 2; k <= N; k <<= 1) {
        for (int j = k >> 1; j > 0; j >>= 1) {
            for (int i = tid; i < N; i += 1024) {
                int ixj = i ^ j;
                if (ixj > i) {
                    bool up = ((i & k) == 0);
                    float k0 = key[i], k1 = key[ixj];
                    if ((k0 > k1) == up) {
                        key[i] = k1; key[ixj] = k0;
                        int t = idx[i]; idx[i] = idx[ixj]; idx[ixj] = t;
                    }
                }
            }
            __syncthreads();
        }
    }

    // inclusive scan of exp(key) (Hillis-Steele, 2 elems/thread)
    const int i0 = tid, i1 = tid + 1024;
    ez[i0] = expf(key[i0]);
    ez[i1] = expf(key[i1]);
    __syncthreads();
    for (int off = 1; off < N; off <<= 1) {
        float a0 = ez[i0], a1 = ez[i1];
        float b0 = (i0 >= off) ? ez[i0 - off] : 0.f;
        float b1 = (i1 >= off) ? ez[i1 - off] : 0.f;
        __syncthreads();
        ez[i0] = a0 + b0;
        ez[i1] = a1 + b1;
        __syncthreads();
    }

    // store sorted keys/perm for the prefix kernels
    for (int i = tid; i < N; i += 1024) {
        g_ssort[b * N + i] = key[i];
        g_perm[b * N + i]  = idx[i];
    }

    // per-row coefficients: k_i, c1 = e^{si}/Z, c2 = 1/Z
    const float EzN = ez[N - 1];
    for (int i = tid; i < N; i += 1024) {
        float si = g_si[b * N + i];
        float t = -si;
        int lo = 0, hi = N;
        while (lo < hi) {
            int mid = (lo + hi) >> 1;
            if (key[mid] <= t) lo = mid + 1; else hi = mid;
        }
        int k = lo;                              // #{j : s_j <= -s_i}
        float esi = expf(si);
        float ezk = (k > 0) ? ez[k - 1] : 0.f;
        float Z = fmaf(esi, EzN - ezk, (float)k); // Z >= N, never 0
        g_k[b * N + i]  = k;
        g_c1[b * N + i] = esi / Z;
        g_c2[b * N + i] = 1.f / Z;
    }
}

// ---------------------------------------------------------------------------
// K3a: per-chunk totals of F (exp(s)*hw) and G (hw) in sorted order
// ---------------------------------------------------------------------------
__global__ __launch_bounds__(128) void k_chunks() {
    const int b = blockIdx.y, c = blockIdx.x, d = threadIdx.x;
    __shared__ float sw[CH];
    __shared__ int   sp[CH];
    {
        int r = d;  // CH == blockDim.x == 128
        sw[r] = expf(g_ssort[b * N + c * CH + r]);
        sp[r] = g_perm[b * N + c * CH + r];
    }
    __syncthreads();
    float aF = 0.f, aG = 0.f;
#pragma unroll 4
    for (int r = 0; r < CH; r++) {
        float v = g_hw[((size_t)b * N + sp[r]) * D + d];
        aF = fmaf(sw[r], v, aF);
        aG += v;
    }
    g_chF[(b * NC + c) * D + d] = aF;
    g_chG[(b * NC + c) * D + d] = aG;
}

// K3b: exclusive scan of chunk totals (tiny)
__global__ __launch_bounds__(128) void k_scanchunks() {
    const int b = blockIdx.x, d = threadIdx.x;
    float rF = 0.f, rG = 0.f;
#pragma unroll
    for (int c = 0; c < NC; c++) {
        int o = (b * NC + c) * D + d;
        float tF = g_chF[o], tG = g_chG[o];
        g_chF[o] = rF; g_chG[o] = rG;
        rF += tF; rG += tG;
    }
}

// K3c: write full exclusive prefixes F[k], G[k] (k = 0..N)
__global__ __launch_bounds__(128) void k_prefix() {
    const int b = blockIdx.y, c = blockIdx.x, d = threadIdx.x;
    __shared__ float sw[CH];
    __shared__ int   sp[CH];
    {
        int r = d;
        sw[r] = expf(g_ssort[b * N + c * CH + r]);
        sp[r] = g_perm[b * N + c * CH + r];
    }
    __syncthreads();
    float aF = g_chF[(b * NC + c) * D + d];
    float aG = g_chG[(b * NC + c) * D + d];
#pragma unroll 4
    for (int r = 0; r < CH; r++) {
        int k = c * CH + r;
        g_F[((size_t)b * (N + 1) + k) * D + d] = aF;
        g_G[((size_t)b * (N + 1) + k) * D + d] = aG;
        float v = g_hw[((size_t)b * N + sp[r]) * D + d];
        aF = fmaf(sw[r], v, aF);
        aG += v;
    }
    if (c == NC - 1) {
        g_F[((size_t)b * (N + 1) + N) * D + d] = aF;
        g_G[((size_t)b * (N + 1) + N) * D + d] = aG;
    }
}

// ---------------------------------------------------------------------------
// K4: out[b,i,d] = relu(c1_i*(F_N[d]-F[k_i][d]) + c2_i*G[k_i][d])
// ---------------------------------------------------------------------------
constexpr int RI = 32;
__global__ __launch_bounds__(128) void k_out(float* __restrict__ out) {
    const int b = blockIdx.y;
    const int i0 = blockIdx.x * RI;
    const int d = threadIdx.x;
    const float FN = g_F[((size_t)b * (N + 1) + N) * D + d];
#pragma unroll 2
    for (int ii = 0; ii < RI; ii++) {
        int i = i0 + ii;
        int k = __ldg(&g_k[b * N + i]);
        float c1 = __ldg(&g_c1[b * N + i]);
        float c2 = __ldg(&g_c2[b * N + i]);
        size_t off = ((size_t)b * (N + 1) + k) * D + d;
        float num = fmaf(c1, FN - g_F[off], c2 * g_G[off]);
        out[((size_t)b * N + i) * D + d] = fmaxf(num, 0.f);
    }
}

// ---------------------------------------------------------------------------
extern "C" void kernel_launch(void* const* d_in, const int* in_sizes, int n_in,
                              void* d_out, int out_size) {
    const float* h = nullptr;
    const float* W = nullptr;
    const float* a = nullptr;
    for (int i = 0; i < n_in; i++) {
        if (in_sizes[i] == B * N * D)      h = (const float*)d_in[i];
        else if (in_sizes[i] == D * D)     W = (const float*)d_in[i];
        else if (in_sizes[i] == 2 * D)     a = (const float*)d_in[i];
    }
    float* out = (float*)d_out;

    k_hw<<<(B * N) / BM, 256>>>(h, W, a);
    k_sort<<<B, 1024>>>();
    k_chunks<<<dim3(NC, B), 128>>>();
    k_scanchunks<<<B, 128>>>();
    k_prefix<<<dim3(NC, B), 128>>>();
    k_out<<<dim3(N / RI, B), 128>>>(out);
}